// round 9
// baseline (speedup 1.0000x reference)
#include <cuda_runtime.h>
#include <cstdint>
#include <cstddef>

#define B_ 1024
#define G_ 256
#define K_ 256
#define E_ 64
#define BETA_F 0.05f

// ---------------- scratch (__device__ globals: no runtime allocation) ----------
__device__ float gM [K_*E_*E_];    // 4 MB : M_k = W_k^T W_k
__device__ float gS6[K_*E_*E_];    // 4 MB : sum_{j=0..5} A^j
__device__ float gWL[K_*G_*E_];    // 64 MB: WL_k = W_k * L_k  (R_k = L L^T)
__device__ float gV [K_*E_];       // 64KB : v_k = mu_k W_k
__device__ float gVL[K_*E_];       // 64KB : vl_k = v_k L_k
__device__ float gMunorm[K_];
__device__ float gScore[B_*K_];    // 1 MB
__device__ int   gKmax[B_];

// ---------------- K1: per-k  M, v, ||mu_k||^2 ----------------------------------
__global__ __launch_bounds__(256) void k1_prep(const float* __restrict__ mu,
                                               const float* __restrict__ w)
{
    int k = blockIdx.x;
    int t = threadIdx.x;
    __shared__ float Ws[64*64];   // [g][e] chunk of W_k
    __shared__ float mus[64];
    __shared__ float red[64];
    float acc[16];
#pragma unroll
    for (int i = 0; i < 16; i++) acc[i] = 0.f;
    float vacc = 0.f, mn = 0.f;
    const float* wk = w + (size_t)k * G_ * E_;
    for (int gc = 0; gc < G_; gc += 64) {
        const float* src = wk + (size_t)gc * E_;   // contiguous 4096 floats
        for (int idx = t; idx < 4096; idx += 256) Ws[idx] = src[idx];
        if (t < 64) mus[t] = mu[(size_t)(gc + t) * K_ + k];
        __syncthreads();
#pragma unroll
        for (int r = 0; r < 16; r++) {
            int idx = t + (r << 8);
            int e = idx >> 6, f = idx & 63;
            float a = 0.f;
#pragma unroll 16
            for (int g = 0; g < 64; g++) a += Ws[g*64 + e] * Ws[g*64 + f];
            acc[r] += a;
        }
        if (t < 64) {
            float va = 0.f;
#pragma unroll 16
            for (int g = 0; g < 64; g++) va += mus[g] * Ws[g*64 + t];
            vacc += va;
            mn += mus[t] * mus[t];
        }
        __syncthreads();
    }
    float* Mk = gM + (size_t)k * 4096;
#pragma unroll
    for (int r = 0; r < 16; r++) Mk[t + (r << 8)] = acc[r];
    if (t < 64) { gV[k*E_ + t] = vacc; red[t] = mn; }
    __syncthreads();
    if (t == 0) { float s = 0.f; for (int i = 0; i < 64; i++) s += red[i]; gMunorm[k] = s; }
}

// ---------------- K2: per-k  S6, R, chol(R)=LL^T, WL = W*L, vl = v*L -----------
// S_{t+1} = I + A*S_t, A = (1-b)I - b*M.  S_1 = I; after 4 iters Ss = S5.
// S6 = I + (1-b)S5 - b*(M*S5).  R = 2b*S5 - b^2*(M*S5)*S5  (SPD for this data).
__global__ __launch_bounds__(256) void k2_poly(const float* __restrict__ w)
{
    int k = blockIdx.x;
    int t = threadIdx.x;
    __shared__ float Ms[64*64];
    __shared__ float Ss[64*64];
    const float* Mk = gM + (size_t)k * 4096;
    for (int idx = t; idx < 4096; idx += 256) {
        Ms[idx] = Mk[idx];
        Ss[idx] = ((idx >> 6) == (idx & 63)) ? 1.f : 0.f;
    }
    __syncthreads();
    for (int it = 0; it < 4; it++) {
        float val[16];
#pragma unroll
        for (int r = 0; r < 16; r++) {
            int idx = t + (r << 8);
            int e = idx >> 6, f = idx & 63;
            float a = 0.f;
#pragma unroll 16
            for (int g = 0; g < 64; g++) a += Ms[e*64 + g] * Ss[g*64 + f];
            float v = (1.f - BETA_F) * Ss[idx] - BETA_F * a;
            if (e == f) v += 1.f;
            val[r] = v;
        }
        __syncthreads();
#pragma unroll
        for (int r = 0; r < 16; r++) Ss[t + (r << 8)] = val[r];
        __syncthreads();
    }
    // Ss = S5. ms5 = M*S5 (regs); S6 -> gmem; Ms := ms5.
    float ms5[16];
#pragma unroll
    for (int r = 0; r < 16; r++) {
        int idx = t + (r << 8);
        int e = idx >> 6, f = idx & 63;
        float a = 0.f;
#pragma unroll 16
        for (int g = 0; g < 64; g++) a += Ms[e*64 + g] * Ss[g*64 + f];
        ms5[r] = a;
        float s6 = (1.f - BETA_F) * Ss[idx] - BETA_F * a;
        if (e == f) s6 += 1.f;
        gS6[(size_t)k*4096 + idx] = s6;
    }
    __syncthreads();
#pragma unroll
    for (int r = 0; r < 16; r++) Ms[t + (r << 8)] = ms5[r];
    __syncthreads();
    // R = 2b*S5 - b^2*(M*S5)*S5  -> into Ss (overwrite S5 after full read)
    float rv[16];
#pragma unroll
    for (int r = 0; r < 16; r++) {
        int idx = t + (r << 8);
        int e = idx >> 6, f = idx & 63;
        float q = 0.f;
#pragma unroll 16
        for (int g = 0; g < 64; g++) q += Ms[e*64 + g] * Ss[g*64 + f];
        rv[r] = 2.f*BETA_F*Ss[idx] - BETA_F*BETA_F*q;
    }
    __syncthreads();
#pragma unroll
    for (int r = 0; r < 16; r++) Ss[t + (r << 8)] = rv[r];
    __syncthreads();

    // In-place Cholesky (lower) of Ss. Right-looking, rank-1 updates.
    for (int j = 0; j < 64; j++) {
        if (t == 0) Ss[j*65] = sqrtf(Ss[j*65]);
        __syncthreads();
        float dinv = __frcp_rn(Ss[j*65]);
        if (t > j && t < 64) Ss[t*64 + j] *= dinv;
        __syncthreads();
        for (int idx = t; idx < 4096; idx += 256) {
            int i = idx >> 6, c = idx & 63;
            if (c > j && c <= i) Ss[i*64 + c] -= Ss[i*64 + j] * Ss[c*64 + j];
        }
        __syncthreads();
    }
    // zero upper triangle so the WL GEMM can run full-range (unrollable)
    for (int idx = t; idx < 4096; idx += 256) {
        int f = idx >> 6, e = idx & 63;
        if (f < e) Ss[idx] = 0.f;
    }
    __syncthreads();

    // vl = v * L   (vl[e] = sum_f v[f] * L[f][e])
    if (t < 64) {
        float a = 0.f;
#pragma unroll 16
        for (int f = 0; f < 64; f++) a += gV[k*E_ + f] * Ss[f*64 + t];
        gVL[k*E_ + t] = a;
    }

    // WL = W * L, in 64-row chunks staged through Ms
    const float* wk = w + (size_t)k * G_ * E_;
    float* wlk = gWL + (size_t)k * G_ * E_;
    for (int gc = 0; gc < G_; gc += 64) {
        __syncthreads();
        const float* src = wk + (size_t)gc * E_;   // contiguous 4096 floats
        for (int idx = t; idx < 4096; idx += 256) Ms[idx] = src[idx];
        __syncthreads();
#pragma unroll
        for (int r = 0; r < 16; r++) {
            int idx = t + (r << 8);
            int g = idx >> 6, e = idx & 63;
            float a = 0.f;
#pragma unroll 16
            for (int f = 0; f < 64; f++) a += Ms[g*64 + f] * Ss[f*64 + e];
            wlk[(size_t)(gc + g)*E_ + e] = a;
        }
    }
}

// ---------------- K3: C = X*WL_k; score = 2*(x.mu_k) + ||C - vl_k||^2 - ||mu_k||^2
// grid (16, 256): 64-row b-tile x one k. 128 thr, 8x4 micro-tiles. Single GEMM,
// square-sum epilogue (quadform GEMM eliminated via Cholesky restructure).
__global__ __launch_bounds__(128) void k3_score(const float* __restrict__ X,
                                                const float* __restrict__ mu)
{
    const int k  = blockIdx.y;
    const int b0 = blockIdx.x * 64;
    const int t  = threadIdx.x;
    const int tx = t & 15;   // e-group (e = tx*4..tx*4+3)
    const int ty = t >> 4;   // b-group (b = ty*8..ty*8+7)

    __shared__ float XsT[32*68];   // [g][b], padded
    __shared__ float WLs[32*64];   // [g][e]
    __shared__ float mus[32];
    __shared__ float qpart[64];

    float uacc[8][4];
#pragma unroll
    for (int i = 0; i < 8; i++)
#pragma unroll
        for (int l = 0; l < 4; l++) uacc[i][l] = 0.f;
    float dacc = 0.f;

    const float* wlk = gWL + (size_t)k * G_ * E_;
    for (int gc = 0; gc < G_; gc += 32) {
        for (int idx = t; idx < 2048; idx += 128) {
            int i = idx >> 5, j = idx & 31;
            XsT[j*68 + i] = X[(size_t)(b0 + i) * G_ + gc + j];
        }
        {
            const float* src = wlk + (size_t)gc * E_;   // contiguous 2048
            for (int idx = t; idx < 2048; idx += 128) WLs[idx] = src[idx];
        }
        if (t < 32) mus[t] = mu[(size_t)(gc + t) * K_ + k];
        __syncthreads();
#pragma unroll
        for (int j = 0; j < 32; j++) {
            float4 a0 = *(const float4*)&XsT[j*68 + ty*8];
            float4 a1 = *(const float4*)&XsT[j*68 + ty*8 + 4];
            float4 wv = *(const float4*)&WLs[j*64 + tx*4];
            uacc[0][0] += a0.x*wv.x; uacc[0][1] += a0.x*wv.y; uacc[0][2] += a0.x*wv.z; uacc[0][3] += a0.x*wv.w;
            uacc[1][0] += a0.y*wv.x; uacc[1][1] += a0.y*wv.y; uacc[1][2] += a0.y*wv.z; uacc[1][3] += a0.y*wv.w;
            uacc[2][0] += a0.z*wv.x; uacc[2][1] += a0.z*wv.y; uacc[2][2] += a0.z*wv.z; uacc[2][3] += a0.z*wv.w;
            uacc[3][0] += a0.w*wv.x; uacc[3][1] += a0.w*wv.y; uacc[3][2] += a0.w*wv.z; uacc[3][3] += a0.w*wv.w;
            uacc[4][0] += a1.x*wv.x; uacc[4][1] += a1.x*wv.y; uacc[4][2] += a1.x*wv.z; uacc[4][3] += a1.x*wv.w;
            uacc[5][0] += a1.y*wv.x; uacc[5][1] += a1.y*wv.y; uacc[5][2] += a1.y*wv.z; uacc[5][3] += a1.y*wv.w;
            uacc[6][0] += a1.z*wv.x; uacc[6][1] += a1.z*wv.y; uacc[6][2] += a1.z*wv.z; uacc[6][3] += a1.z*wv.w;
            uacc[7][0] += a1.w*wv.x; uacc[7][1] += a1.w*wv.y; uacc[7][2] += a1.w*wv.z; uacc[7][3] += a1.w*wv.w;
        }
        if (t < 64) {   // d_b = x_b . mu_k partial
            float dd = 0.f;
#pragma unroll
            for (int j = 0; j < 32; j++) dd += XsT[j*68 + t] * mus[j];
            dacc += dd;
        }
        __syncthreads();
    }

    // epilogue: p_b = sum_e (C[b][e] - vl[e])^2, reduced across the 16 e-lanes
    const float4 vl4 = *(const float4*)&gVL[k*E_ + tx*4];
    float p[8];
#pragma unroll
    for (int i = 0; i < 8; i++) {
        float c0 = uacc[i][0] - vl4.x;
        float c1 = uacc[i][1] - vl4.y;
        float c2 = uacc[i][2] - vl4.z;
        float c3 = uacc[i][3] - vl4.w;
        p[i] = c0*c0 + c1*c1 + c2*c2 + c3*c3;
#pragma unroll
        for (int ofs = 8; ofs > 0; ofs >>= 1)
            p[i] += __shfl_down_sync(0xffffffffu, p[i], ofs, 16);
    }
    if (tx == 0) {
#pragma unroll
        for (int i = 0; i < 8; i++) qpart[ty*8 + i] = p[i];
    }
    __syncthreads();
    if (t < 64) {
        // maximize  -||dx||^2  <=>  maximize  2*d + uRu - ||mu_k||^2
        gScore[(size_t)(b0 + t) * K_ + k] = 2.f*dacc + qpart[t] - gMunorm[k];
    }
}

// ---------------- K4: argmax over k (first-max tie-break, like jnp.argmax) -----
__global__ __launch_bounds__(256) void k4_argmax()
{
    int b = blockIdx.x;
    int t = threadIdx.x;
    __shared__ float sv[256];
    __shared__ int   si[256];
    sv[t] = gScore[(size_t)b * K_ + t];
    si[t] = t;
    __syncthreads();
    for (int s = 128; s > 0; s >>= 1) {
        if (t < s) {
            float v2 = sv[t + s]; int i2 = si[t + s];
            if (v2 > sv[t] || (v2 == sv[t] && i2 < si[t])) { sv[t] = v2; si[t] = i2; }
        }
        __syncthreads();
    }
    if (t == 0) gKmax[b] = si[0];
}

// ---------------- K5: decode winner: y = beta*u*S6*W^T + mu_k ------------------
__global__ __launch_bounds__(256) void k5_decode(const float* __restrict__ X,
                                                 const float* __restrict__ mu,
                                                 const float* __restrict__ w,
                                                 float* __restrict__ y)
{
    int b = blockIdx.x;
    int t = threadIdx.x;
    __shared__ float upart[4][64];
    __shared__ float us[64];
    __shared__ float z6[64];
    int k = gKmax[b];
    const float* wk = w + (size_t)k * G_ * E_;

    {   // u[e] = sum_g X[b][g]*wk[g][e] - v[k][e], 4-way g split
        int e = t & 63, gq = t >> 6;
        float a = 0.f;
        const float* xb = X + (size_t)b * G_;
#pragma unroll 16
        for (int g = gq*64; g < gq*64 + 64; g++) a += xb[g] * wk[(size_t)g*E_ + e];
        upart[gq][e] = a;
    }
    __syncthreads();
    if (t < 64) us[t] = upart[0][t] + upart[1][t] + upart[2][t] + upart[3][t] - gV[k*E_ + t];
    __syncthreads();
    if (t < 64) {
        const float* S6k = gS6 + (size_t)k * 4096;
        float a = 0.f;
#pragma unroll 16
        for (int f = 0; f < 64; f++) a += us[f] * S6k[f*64 + t];
        z6[t] = BETA_F * a;
    }
    __syncthreads();
    {
        int g = t;
        float a = 0.f;
        const float* wg = wk + (size_t)g * E_;
#pragma unroll
        for (int e = 0; e < 64; e++) a += z6[e] * wg[e];
        y[(size_t)b * G_ + g] = a + mu[(size_t)g * K_ + k];
    }
}

// ---------------- launch --------------------------------------------------------
extern "C" void kernel_launch(void* const* d_in, const int* in_sizes, int n_in,
                              void* d_out, int out_size)
{
    const float* X  = (const float*)d_in[0];   // images (B,G)
    const float* mu = (const float*)d_in[1];   // (G,K)
    const float* w  = (const float*)d_in[2];   // (K,G,E)
    float* y = (float*)d_out;                  // (B,G)

    k1_prep<<<K_, 256>>>(mu, w);
    k2_poly<<<K_, 256>>>(w);
    dim3 g3(B_/64, K_);
    k3_score<<<g3, 128>>>(X, mu);
    k4_argmax<<<B_, 256>>>();
    k5_decode<<<B_, 256>>>(X, mu, w, y);
}

// round 10
// speedup vs baseline: 1.0305x; 1.0305x over previous
#include <cuda_runtime.h>
#include <cstdint>
#include <cstddef>

#define B_ 1024
#define G_ 256
#define K_ 256
#define E_ 64
#define BETA_F 0.05f

// ---------------- scratch (__device__ globals: no runtime allocation) ----------
__device__ float gM [K_*E_*E_];    // 4 MB : M_k = W_k^T W_k
__device__ float gS6[K_*E_*E_];    // 4 MB : sum_{j=0..5} A^j
__device__ float gWL[K_*G_*E_];    // 64 MB: WL_k = W_k * L_k  (R_k = L L^T)
__device__ float gV [K_*E_];       // 64KB : v_k = mu_k W_k
__device__ float gVL[K_*E_];       // 64KB : vl_k = v_k L_k
__device__ float gMunorm[K_];
__device__ float gScore[B_*K_];    // 1 MB
__device__ int   gKmax[B_];

// ---------------- tf32 helpers -------------------------------------------------
__device__ __forceinline__ float tf32r(float x) {
    uint32_t r; asm("cvt.rna.tf32.f32 %0, %1;" : "=r"(r) : "f"(x));
    return __uint_as_float(r);
}
__device__ __forceinline__ void mma_tf32(float* c, const float* a, float b0, float b1) {
    asm volatile(
        "mma.sync.aligned.m16n8k8.row.col.f32.tf32.tf32.f32 "
        "{%0,%1,%2,%3},{%4,%5,%6,%7},{%8,%9},{%0,%1,%2,%3};"
        : "+f"(c[0]), "+f"(c[1]), "+f"(c[2]), "+f"(c[3])
        : "r"(__float_as_uint(a[0])), "r"(__float_as_uint(a[1])),
          "r"(__float_as_uint(a[2])), "r"(__float_as_uint(a[3])),
          "r"(__float_as_uint(b0)),  "r"(__float_as_uint(b1)));
}

// ---------------- K1: per-k  M, v, ||mu_k||^2 ----------------------------------
__global__ __launch_bounds__(256) void k1_prep(const float* __restrict__ mu,
                                               const float* __restrict__ w)
{
    int k = blockIdx.x;
    int t = threadIdx.x;
    __shared__ float Ws[64*64];   // [g][e] chunk of W_k
    __shared__ float mus[64];
    __shared__ float red[64];
    float acc[16];
#pragma unroll
    for (int i = 0; i < 16; i++) acc[i] = 0.f;
    float vacc = 0.f, mn = 0.f;
    const float* wk = w + (size_t)k * G_ * E_;
    for (int gc = 0; gc < G_; gc += 64) {
        const float* src = wk + (size_t)gc * E_;   // contiguous 4096 floats
        for (int idx = t; idx < 4096; idx += 256) Ws[idx] = src[idx];
        if (t < 64) mus[t] = mu[(size_t)(gc + t) * K_ + k];
        __syncthreads();
#pragma unroll
        for (int r = 0; r < 16; r++) {
            int idx = t + (r << 8);
            int e = idx >> 6, f = idx & 63;
            float a = 0.f;
#pragma unroll 16
            for (int g = 0; g < 64; g++) a += Ws[g*64 + e] * Ws[g*64 + f];
            acc[r] += a;
        }
        if (t < 64) {
            float va = 0.f;
#pragma unroll 16
            for (int g = 0; g < 64; g++) va += mus[g] * Ws[g*64 + t];
            vacc += va;
            mn += mus[t] * mus[t];
        }
        __syncthreads();
    }
    float* Mk = gM + (size_t)k * 4096;
#pragma unroll
    for (int r = 0; r < 16; r++) Mk[t + (r << 8)] = acc[r];
    if (t < 64) { gV[k*E_ + t] = vacc; red[t] = mn; }
    __syncthreads();
    if (t == 0) { float s = 0.f; for (int i = 0; i < 64; i++) s += red[i]; gMunorm[k] = s; }
}

// ---------------- K2: per-k  S6, R, chol(R)=LL^T, WL = W*L, vl = v*L -----------
__global__ __launch_bounds__(256) void k2_poly(const float* __restrict__ w)
{
    int k = blockIdx.x;
    int t = threadIdx.x;
    __shared__ float Ms[64*64];
    __shared__ float Ss[64*64];
    const float* Mk = gM + (size_t)k * 4096;
    for (int idx = t; idx < 4096; idx += 256) {
        Ms[idx] = Mk[idx];
        Ss[idx] = ((idx >> 6) == (idx & 63)) ? 1.f : 0.f;
    }
    __syncthreads();
    for (int it = 0; it < 4; it++) {
        float val[16];
#pragma unroll
        for (int r = 0; r < 16; r++) {
            int idx = t + (r << 8);
            int e = idx >> 6, f = idx & 63;
            float a = 0.f;
#pragma unroll 16
            for (int g = 0; g < 64; g++) a += Ms[e*64 + g] * Ss[g*64 + f];
            float v = (1.f - BETA_F) * Ss[idx] - BETA_F * a;
            if (e == f) v += 1.f;
            val[r] = v;
        }
        __syncthreads();
#pragma unroll
        for (int r = 0; r < 16; r++) Ss[t + (r << 8)] = val[r];
        __syncthreads();
    }
    // Ss = S5. ms5 = M*S5 (regs); S6 -> gmem; Ms := ms5.
    float ms5[16];
#pragma unroll
    for (int r = 0; r < 16; r++) {
        int idx = t + (r << 8);
        int e = idx >> 6, f = idx & 63;
        float a = 0.f;
#pragma unroll 16
        for (int g = 0; g < 64; g++) a += Ms[e*64 + g] * Ss[g*64 + f];
        ms5[r] = a;
        float s6 = (1.f - BETA_F) * Ss[idx] - BETA_F * a;
        if (e == f) s6 += 1.f;
        gS6[(size_t)k*4096 + idx] = s6;
    }
    __syncthreads();
#pragma unroll
    for (int r = 0; r < 16; r++) Ms[t + (r << 8)] = ms5[r];
    __syncthreads();
    // R = 2b*S5 - b^2*(M*S5)*S5  -> into Ss
    float rv[16];
#pragma unroll
    for (int r = 0; r < 16; r++) {
        int idx = t + (r << 8);
        int e = idx >> 6, f = idx & 63;
        float q = 0.f;
#pragma unroll 16
        for (int g = 0; g < 64; g++) q += Ms[e*64 + g] * Ss[g*64 + f];
        rv[r] = 2.f*BETA_F*Ss[idx] - BETA_F*BETA_F*q;
    }
    __syncthreads();
#pragma unroll
    for (int r = 0; r < 16; r++) Ss[t + (r << 8)] = rv[r];
    __syncthreads();

    // In-place Cholesky (lower) of Ss.
    for (int j = 0; j < 64; j++) {
        if (t == 0) Ss[j*65] = sqrtf(Ss[j*65]);
        __syncthreads();
        float dinv = __frcp_rn(Ss[j*65]);
        if (t > j && t < 64) Ss[t*64 + j] *= dinv;
        __syncthreads();
        for (int idx = t; idx < 4096; idx += 256) {
            int i = idx >> 6, c = idx & 63;
            if (c > j && c <= i) Ss[i*64 + c] -= Ss[i*64 + j] * Ss[c*64 + j];
        }
        __syncthreads();
    }
    for (int idx = t; idx < 4096; idx += 256) {
        int f = idx >> 6, e = idx & 63;
        if (f < e) Ss[idx] = 0.f;
    }
    __syncthreads();

    // vl = v * L
    if (t < 64) {
        float a = 0.f;
#pragma unroll 16
        for (int f = 0; f < 64; f++) a += gV[k*E_ + f] * Ss[f*64 + t];
        gVL[k*E_ + t] = a;
    }

    // WL = W * L, staged through Ms
    const float* wk = w + (size_t)k * G_ * E_;
    float* wlk = gWL + (size_t)k * G_ * E_;
    for (int gc = 0; gc < G_; gc += 64) {
        __syncthreads();
        const float* src = wk + (size_t)gc * E_;
        for (int idx = t; idx < 4096; idx += 256) Ms[idx] = src[idx];
        __syncthreads();
#pragma unroll
        for (int r = 0; r < 16; r++) {
            int idx = t + (r << 8);
            int g = idx >> 6, e = idx & 63;
            float a = 0.f;
#pragma unroll 16
            for (int f = 0; f < 64; f++) a += Ms[g*64 + f] * Ss[f*64 + e];
            wlk[(size_t)(gc + g)*E_ + e] = a;
        }
    }
}

// ---------------- K3: 3xTF32 tensor-core GEMM + square-sum epilogue ------------
// C = X * [WL_k | mu_k] via mma.sync m16n8k8 (hi/lo split, 3 products).
// score_b = 2*C[b][64] + ||C[b][0:64] - vl_k||^2 - ||mu_k||^2.
// Block: 64 b-rows x one k, 256 thr = 8 warps (4 b x 2 e), warp = 16b x 32e.
__global__ __launch_bounds__(256) void k3_score(const float* __restrict__ X,
                                                const float* __restrict__ mu)
{
    const int k  = blockIdx.y;
    const int b0 = blockIdx.x * 64;
    const int t  = threadIdx.x;
    const int lane = t & 31, wid = t >> 5;
    const int wb = wid & 3;        // b quadrant: rows wb*16..wb*16+15
    const int we = wid >> 2;       // e half:     cols we*32..we*32+31
    const int gID = lane >> 2, tig = lane & 3;

    __shared__ float Xh[64*36];    // X hi split, row stride 36 (conflict-free frags)
    __shared__ float Xl[64*36];
    __shared__ float Wh[32*72];    // [g][e] WL hi split + mu in col 64; stride 72
    __shared__ float Wl[32*72];
    __shared__ float vls[64];
    __shared__ float qp[64];

    // one-time: vl and zero the dead B columns 65..71
    if (t < 64) vls[t] = gVL[k*E_ + t];
    if (t < 32) {
#pragma unroll
        for (int c = 65; c < 72; c++) { Wh[t*72 + c] = 0.f; Wl[t*72 + c] = 0.f; }
    }

    float acc[5][4];
#pragma unroll
    for (int i = 0; i < 5; i++)
#pragma unroll
        for (int l = 0; l < 4; l++) acc[i][l] = 0.f;

    const float* wlk = gWL + (size_t)k * G_ * E_;
    for (int gc = 0; gc < G_; gc += 32) {
        // fill X tiles (split on the fly): 2048 elems = 512 float4
#pragma unroll
        for (int s = 0; s < 2; s++) {
            int idx = t*4 + s*1024;
            int i = idx >> 5, j = idx & 31;
            float4 xv = *(const float4*)&X[(size_t)(b0 + i)*G_ + gc + j];
            float hx = tf32r(xv.x), hy = tf32r(xv.y), hz = tf32r(xv.z), hw = tf32r(xv.w);
            *(float4*)&Xh[i*36 + j] = make_float4(hx, hy, hz, hw);
            *(float4*)&Xl[i*36 + j] = make_float4(tf32r(xv.x - hx), tf32r(xv.y - hy),
                                                  tf32r(xv.z - hz), tf32r(xv.w - hw));
        }
        // fill WL tiles
#pragma unroll
        for (int s = 0; s < 2; s++) {
            int idx = t*4 + s*1024;
            int g = idx >> 6, e = idx & 63;
            float4 wv = *(const float4*)&wlk[(size_t)(gc + g)*E_ + e];
            float hx = tf32r(wv.x), hy = tf32r(wv.y), hz = tf32r(wv.z), hw = tf32r(wv.w);
            *(float4*)&Wh[g*72 + e] = make_float4(hx, hy, hz, hw);
            *(float4*)&Wl[g*72 + e] = make_float4(tf32r(wv.x - hx), tf32r(wv.y - hy),
                                                  tf32r(wv.z - hz), tf32r(wv.w - hw));
        }
        // mu -> B column 64
        if (t < 32) {
            float m = mu[(size_t)(gc + t)*K_ + k];
            float mh = tf32r(m);
            Wh[t*72 + 64] = mh;
            Wl[t*72 + 64] = tf32r(m - mh);
        }
        __syncthreads();

#pragma unroll
        for (int ks = 0; ks < 4; ks++) {
            float ah[4], al[4];
            int ar = wb*16 + gID;
            int ac = ks*8 + tig;
            ah[0] = Xh[ar*36 + ac];     ah[1] = Xh[(ar+8)*36 + ac];
            ah[2] = Xh[ar*36 + ac + 4]; ah[3] = Xh[(ar+8)*36 + ac + 4];
            al[0] = Xl[ar*36 + ac];     al[1] = Xl[(ar+8)*36 + ac];
            al[2] = Xl[ar*36 + ac + 4]; al[3] = Xl[(ar+8)*36 + ac + 4];
#pragma unroll
            for (int ni = 0; ni < 5; ni++) {
                if (ni == 4 && we == 0) continue;   // mu column handled by e-half 1 only
                int bc = we*32 + ni*8 + gID;        // ni==4 (we==1) -> 64+gID
                int br = ks*8 + tig;
                float bh0 = Wh[br*72 + bc], bh1 = Wh[(br+4)*72 + bc];
                float bl0 = Wl[br*72 + bc], bl1 = Wl[(br+4)*72 + bc];
                mma_tf32(acc[ni], ah, bh0, bh1);
                mma_tf32(acc[ni], ah, bl0, bl1);
                mma_tf32(acc[ni], al, bh0, bh1);
            }
        }
        __syncthreads();
    }

    // epilogue: per-lane squared-distance partials over owned (row, col) pairs
    float p1 = 0.f, p2 = 0.f;
#pragma unroll
    for (int ni = 0; ni < 4; ni++) {
        int col = we*32 + ni*8 + 2*tig;
        float v0 = vls[col], v1 = vls[col + 1];
        float d0 = acc[ni][0] - v0, d1 = acc[ni][1] - v1;
        float d2 = acc[ni][2] - v0, d3 = acc[ni][3] - v1;
        p1 += d0*d0 + d1*d1;
        p2 += d2*d2 + d3*d3;
    }
    p1 += __shfl_xor_sync(0xffffffffu, p1, 1);
    p1 += __shfl_xor_sync(0xffffffffu, p1, 2);
    p2 += __shfl_xor_sync(0xffffffffu, p2, 1);
    p2 += __shfl_xor_sync(0xffffffffu, p2, 2);

    int r1 = wb*16 + gID, r2 = r1 + 8;
    if (we == 0 && tig == 0) { qp[r1] = p1; qp[r2] = p2; }
    __syncthreads();
    if (we == 1 && tig == 0) {
        float mn = gMunorm[k];
        // acc[4][0]/acc[4][2] hold x.mu for rows r1/r2 (B col 64)
        gScore[(size_t)(b0 + r1)*K_ + k] = 2.f*acc[4][0] + (qp[r1] + p1) - mn;
        gScore[(size_t)(b0 + r2)*K_ + k] = 2.f*acc[4][2] + (qp[r2] + p2) - mn;
    }
}

// ---------------- K4: argmax over k (first-max tie-break, like jnp.argmax) -----
__global__ __launch_bounds__(256) void k4_argmax()
{
    int b = blockIdx.x;
    int t = threadIdx.x;
    __shared__ float sv[256];
    __shared__ int   si[256];
    sv[t] = gScore[(size_t)b * K_ + t];
    si[t] = t;
    __syncthreads();
    for (int s = 128; s > 0; s >>= 1) {
        if (t < s) {
            float v2 = sv[t + s]; int i2 = si[t + s];
            if (v2 > sv[t] || (v2 == sv[t] && i2 < si[t])) { sv[t] = v2; si[t] = i2; }
        }
        __syncthreads();
    }
    if (t == 0) gKmax[b] = si[0];
}

// ---------------- K5: decode winner: y = beta*u*S6*W^T + mu_k ------------------
__global__ __launch_bounds__(256) void k5_decode(const float* __restrict__ X,
                                                 const float* __restrict__ mu,
                                                 const float* __restrict__ w,
                                                 float* __restrict__ y)
{
    int b = blockIdx.x;
    int t = threadIdx.x;
    __shared__ float upart[4][64];
    __shared__ float us[64];
    __shared__ float z6[64];
    int k = gKmax[b];
    const float* wk = w + (size_t)k * G_ * E_;

    {   // u[e] = sum_g X[b][g]*wk[g][e] - v[k][e], 4-way g split
        int e = t & 63, gq = t >> 6;
        float a = 0.f;
        const float* xb = X + (size_t)b * G_;
#pragma unroll 16
        for (int g = gq*64; g < gq*64 + 64; g++) a += xb[g] * wk[(size_t)g*E_ + e];
        upart[gq][e] = a;
    }
    __syncthreads();
    if (t < 64) us[t] = upart[0][t] + upart[1][t] + upart[2][t] + upart[3][t] - gV[k*E_ + t];
    __syncthreads();
    if (t < 64) {
        const float* S6k = gS6 + (size_t)k * 4096;
        float a = 0.f;
#pragma unroll 16
        for (int f = 0; f < 64; f++) a += us[f] * S6k[f*64 + t];
        z6[t] = BETA_F * a;
    }
    __syncthreads();
    {
        int g = t;
        float a = 0.f;
        const float* wg = wk + (size_t)g * E_;
#pragma unroll
        for (int e = 0; e < 64; e++) a += z6[e] * wg[e];
        y[(size_t)b * G_ + g] = a + mu[(size_t)g * K_ + k];
    }
}

// ---------------- launch --------------------------------------------------------
extern "C" void kernel_launch(void* const* d_in, const int* in_sizes, int n_in,
                              void* d_out, int out_size)
{
    const float* X  = (const float*)d_in[0];   // images (B,G)
    const float* mu = (const float*)d_in[1];   // (G,K)
    const float* w  = (const float*)d_in[2];   // (K,G,E)
    float* y = (float*)d_out;                  // (B,G)

    k1_prep<<<K_, 256>>>(mu, w);
    k2_poly<<<K_, 256>>>(w);
    dim3 g3(B_/64, K_);
    k3_score<<<g3, 256>>>(X, mu);
    k4_argmax<<<B_, 256>>>();
    k5_decode<<<B_, 256>>>(X, mu, w, y);
}